// round 16
// baseline (speedup 1.0000x reference)
#include <cuda_runtime.h>
#include <math_constants.h>
#include <cstdint>

// Problem constants
#define BB 2
#define TT 4096
#define EE 768
#define HH 12
#define SS 64            // head dim
#define WW 256           // one-sided window
#define MM (BB*TT)       // 8192 rows in projection GEMM

// Scratch for projections, head-major layout [B, H, T, S], tf32-rounded floats
__device__ float g_q[BB*HH*TT*SS];
__device__ float g_k[BB*HH*TT*SS];
__device__ float g_v[BB*HH*TT*SS];

// ---------------------------------------------------------------------------
// tf32 helpers
// ---------------------------------------------------------------------------
__device__ __forceinline__ uint32_t f2tf32(float f) {
    uint32_t u;
    asm("cvt.rna.tf32.f32 %0, %1;" : "=r"(u) : "f"(f));
    return u;
}
__device__ __forceinline__ float f2tf32f(float f) {
    return __uint_as_float(f2tf32(f));
}

// mma.sync m16n8k8 tf32, row.col, fp32 accumulate (in-place C)
__device__ __forceinline__ void mma_tf32(float* c, const uint32_t* a, const uint32_t* b) {
    asm volatile(
        "mma.sync.aligned.m16n8k8.row.col.f32.tf32.tf32.f32 "
        "{%0,%1,%2,%3}, {%4,%5,%6,%7}, {%8,%9}, {%0,%1,%2,%3};"
        : "+f"(c[0]), "+f"(c[1]), "+f"(c[2]), "+f"(c[3])
        : "r"(a[0]), "r"(a[1]), "r"(a[2]), "r"(a[3]), "r"(b[0]), "r"(b[1]));
}

// Fragment layouts (m16n8k8 tf32):
//  A (16x8):  a0=(r, c)  a1=(r+8, c)  a2=(r, c+4)  a3=(r+8, c+4)   r=lane/4, c=lane%4
//  B (8x8):   b0=(k, n)  b1=(k+4, n)                               k=lane%4, n=lane/4
//  C (16x8):  c0=(r,2c) c1=(r,2c+1) c2=(r+8,2c) c3=(r+8,2c+1)

// ---------------------------------------------------------------------------
// Kernel 1: QKV projection GEMM on tensor cores (tf32).
// y[m,n] = sum_k x[m,k] * W[n,k]
// BM=128, BN=64(=head), BK=32, 256 threads = 8 warps (4M x 2N), warp tile 32x32.
// R14: register-prefetch pipeline — global loads for tile i+1 issued before
// computing tile i; tf32 conversion ONCE at staging (cvt-at-frag-load of R13
// multiplied cvt work across warps and regressed).
// ---------------------------------------------------------------------------
#define GBK 32
#define GNK (EE/GBK)    // 24

__global__ __launch_bounds__(256) void qkv_gemm_tc(
    const float* __restrict__ x,
    const float* __restrict__ Wq,
    const float* __restrict__ Wk,
    const float* __restrict__ Wv)
{
    const int z = blockIdx.z;
    const float* __restrict__ W = (z == 0) ? Wq : (z == 1) ? Wk : Wv;
    float* __restrict__ outp    = (z == 0) ? g_q : (z == 1) ? g_k : g_v;
    const float scale = (z == 0) ? 0.125f : 1.0f;

    __shared__ float Xs[128][36];   // [m][k], ld=36: frag reads hit 32 banks
    __shared__ float Ws[64][36];    // [n][k]

    const int tid  = threadIdx.x;
    const int wid  = tid >> 5;
    const int lane = tid & 31;
    const int warpM = wid >> 1;     // 0..3
    const int warpN = wid & 1;      // 0..1
    const int m0 = blockIdx.x * 128;
    const int h  = blockIdx.y;      // head == BN block
    const int n0 = h * 64;

    float acc[2][4][4];
#pragma unroll
    for (int mt = 0; mt < 2; mt++)
#pragma unroll
        for (int nt = 0; nt < 4; nt++)
#pragma unroll
            for (int i = 0; i < 4; i++) acc[mt][nt][i] = 0.0f;

    // staging slots: thread covers X rows sr, sr+64 (cols sc..sc+3, sc+16..sc+19)
    // and W row sr (same cols)
    const int sr = tid >> 2;            // 0..63
    const int sc = (tid & 3) * 4;       // 0,4,8,12

    float4 xa, xb, xc, xd, wa, wb;      // prefetch registers

    const float* xrow0 = &x[(m0 + sr     ) * EE + sc];
    const float* xrow1 = &x[(m0 + sr + 64) * EE + sc];
    const float* wrow  = &W[(n0 + sr     ) * EE + sc];

    // prefetch tile 0
    xa = *(const float4*)(xrow0);
    xb = *(const float4*)(xrow0 + 16);
    xc = *(const float4*)(xrow1);
    xd = *(const float4*)(xrow1 + 16);
    wa = *(const float4*)(wrow);
    wb = *(const float4*)(wrow + 16);

    for (int i = 0; i < GNK; i++) {
        // stage prefetched tile (convert to tf32 once per element)
        {
            float4 t;
            t.x=f2tf32f(xa.x); t.y=f2tf32f(xa.y); t.z=f2tf32f(xa.z); t.w=f2tf32f(xa.w);
            *(float4*)&Xs[sr][sc] = t;
            t.x=f2tf32f(xb.x); t.y=f2tf32f(xb.y); t.z=f2tf32f(xb.z); t.w=f2tf32f(xb.w);
            *(float4*)&Xs[sr][sc + 16] = t;
            t.x=f2tf32f(xc.x); t.y=f2tf32f(xc.y); t.z=f2tf32f(xc.z); t.w=f2tf32f(xc.w);
            *(float4*)&Xs[sr + 64][sc] = t;
            t.x=f2tf32f(xd.x); t.y=f2tf32f(xd.y); t.z=f2tf32f(xd.z); t.w=f2tf32f(xd.w);
            *(float4*)&Xs[sr + 64][sc + 16] = t;
            t.x=f2tf32f(wa.x); t.y=f2tf32f(wa.y); t.z=f2tf32f(wa.z); t.w=f2tf32f(wa.w);
            *(float4*)&Ws[sr][sc] = t;
            t.x=f2tf32f(wb.x); t.y=f2tf32f(wb.y); t.z=f2tf32f(wb.z); t.w=f2tf32f(wb.w);
            *(float4*)&Ws[sr][sc + 16] = t;
        }
        __syncthreads();

        // issue global loads for next tile; consumed at next iteration's stage
        if (i + 1 < GNK) {
            const int ko = (i + 1) * GBK;
            xa = *(const float4*)(xrow0 + ko);
            xb = *(const float4*)(xrow0 + ko + 16);
            xc = *(const float4*)(xrow1 + ko);
            xd = *(const float4*)(xrow1 + ko + 16);
            wa = *(const float4*)(wrow + ko);
            wb = *(const float4*)(wrow + ko + 16);
        }

        // compute current tile (4 k-groups of 8)
#pragma unroll
        for (int kk = 0; kk < 4; kk++) {
            const int kb = kk * 8 + (lane & 3);
            uint32_t a[2][4];
#pragma unroll
            for (int mt = 0; mt < 2; mt++) {
                int row = warpM * 32 + mt * 16 + (lane >> 2);
                a[mt][0] = __float_as_uint(Xs[row    ][kb    ]);
                a[mt][1] = __float_as_uint(Xs[row + 8][kb    ]);
                a[mt][2] = __float_as_uint(Xs[row    ][kb + 4]);
                a[mt][3] = __float_as_uint(Xs[row + 8][kb + 4]);
            }
            uint32_t b[4][2];
#pragma unroll
            for (int nt = 0; nt < 4; nt++) {
                int col = warpN * 32 + nt * 8 + (lane >> 2);
                b[nt][0] = __float_as_uint(Ws[col][kb    ]);
                b[nt][1] = __float_as_uint(Ws[col][kb + 4]);
            }
#pragma unroll
            for (int mt = 0; mt < 2; mt++)
#pragma unroll
                for (int nt = 0; nt < 4; nt++)
                    mma_tf32(acc[mt][nt], a[mt], b[nt]);
        }
        __syncthreads();   // all warps done with smem before next stage
    }

    // epilogue: scale, round to tf32, store head-major [B,H,T,S]
#pragma unroll
    for (int mt = 0; mt < 2; mt++) {
        int m = m0 + warpM * 32 + mt * 16 + (lane >> 2);
#pragma unroll
        for (int half = 0; half < 2; half++) {
            int mm = m + half * 8;
            int bI = mm >> 12;
            int t  = mm & (TT - 1);
            float* rowp = outp + ((bI * HH + h) * TT + t) * SS;
#pragma unroll
            for (int nt = 0; nt < 4; nt++) {
                int col = warpN * 32 + nt * 8 + (lane & 3) * 2;
                float2 o;
                o.x = f2tf32f(acc[mt][nt][half * 2 + 0] * scale);
                o.y = f2tf32f(acc[mt][nt][half * 2 + 1] * scale);
                *(float2*)&rowp[col] = o;
            }
        }
    }
}

// ---------------------------------------------------------------------------
// Kernel 2: banded attention on tensor cores, flash-style online softmax.
// CTA = 64 queries / 128 threads (4 warps); 3 CTAs/SM. Each warp owns one m16
// query tile. Keys streamed in 64-chunks spanning [t0-256, t0+320).
// R14: P C-frag -> A-frag conversion via intra-quad shuffles (no smem round
// trip, no __syncwarp):  A(qr, c) with c=qc   comes from lane (lane&~3)|(qc>>1),
// elem parity qc&1;  c=qc+4 from the same lane | 2.
// K/V ld: 68 (K) / 72 (V) -> B-frag reads hit all 32 banks.
// ---------------------------------------------------------------------------
#define QB 64
#define KC 64
#define NCH ((2*WW + QB)/KC)   // 9
#define ATH 128                // attention CTA threads

__global__ __launch_bounds__(ATH, 1) void banded_attn_tc(float* __restrict__ out)
{
    __shared__ float Ks[KC][68];       // [key][dim 0..63]
    __shared__ float Vs[KC][72];       // [key][dim 0..63]

    const int tid  = threadIdx.x;
    const int wid  = tid >> 5;          // 0..3
    const int lane = tid & 31;
    const int t0 = blockIdx.x * QB;
    const int h  = blockIdx.y;
    const int b  = blockIdx.z;
    const int plane = (b * HH + h) * TT;

    const int qr = (lane >> 2);             // 0..7
    const int qc = (lane & 3);              // 0..3
    const int tq0 = t0 + wid * 16 + qr;     // this thread's query row 0
    const int tq1 = tq0 + 8;                //                  ... row 1

    const int psrc0 = (lane & ~3) | (qc >> 1);   // shuffle src for cols qc
    const int psrc1 = psrc0 | 2;                 // shuffle src for cols qc+4
    const bool podd = (qc & 1);

    // persistent Q fragments (already tf32-rounded & scaled by GEMM epilogue)
    uint32_t qa[8][4];
#pragma unroll
    for (int kk = 0; kk < 8; kk++) {
        const float* q0 = g_q + (plane + tq0) * SS + kk * 8 + qc;
        const float* q1 = g_q + (plane + tq1) * SS + kk * 8 + qc;
        qa[kk][0] = __float_as_uint(q0[0]);
        qa[kk][1] = __float_as_uint(q1[0]);
        qa[kk][2] = __float_as_uint(q0[4]);
        qa[kk][3] = __float_as_uint(q1[4]);
    }

    float oa[8][4];
#pragma unroll
    for (int nt = 0; nt < 8; nt++)
#pragma unroll
        for (int i = 0; i < 4; i++) oa[nt][i] = 0.0f;

    float mr0 = -CUDART_INF_F, mr1 = -CUDART_INF_F;
    float l0 = 0.0f, l1 = 0.0f;     // per-thread partial (this quad lane's cols)

    const float4* kp4 = (const float4*)(g_k + (long long)plane * SS);
    const float4* vp4 = (const float4*)(g_v + (long long)plane * SS);
    const int ldc = tid & 15;       // float4 col 0..15  (dim = ldc*4)
    const int ldr = tid >> 4;       // 0..7

    for (int ch = 0; ch < NCH; ch++) {
        const int jbase = t0 - WW + ch * KC;
        if (jbase + KC <= 0 || jbase >= TT) continue;   // block-uniform skip

        // cooperative K/V load (zero-fill out-of-range keys): 64x16 float4 each
#pragma unroll
        for (int it = 0; it < 8; it++) {
            int key = ldr + 8 * it;
            int j = jbase + key;
            bool v = (j >= 0) && (j < TT);
            float4 zero = make_float4(0.f, 0.f, 0.f, 0.f);
            float4 kv = v ? kp4[j * 16 + ldc] : zero;
            float4 vv = v ? vp4[j * 16 + ldc] : zero;
            *(float4*)&Ks[key][ldc * 4] = kv;
            *(float4*)&Vs[key][ldc * 4] = vv;
        }
        __syncthreads();

        // S = Q K^T  (16 x 64 per warp)
        float sacc[8][4];
#pragma unroll
        for (int nt = 0; nt < 8; nt++) {
#pragma unroll
            for (int i = 0; i < 4; i++) sacc[nt][i] = 0.0f;
#pragma unroll
            for (int kk = 0; kk < 8; kk++) {
                uint32_t bb[2];
                bb[0] = __float_as_uint(Ks[nt * 8 + qr][kk * 8 + qc    ]);
                bb[1] = __float_as_uint(Ks[nt * 8 + qr][kk * 8 + qc + 4]);
                mma_tf32(sacc[nt], qa[kk], bb);
            }
        }

        // mask (band + range) and row max
        float rmax0 = -CUDART_INF_F, rmax1 = -CUDART_INF_F;
#pragma unroll
        for (int nt = 0; nt < 8; nt++) {
            int j0 = jbase + nt * 8 + qc * 2;
            int j1 = j0 + 1;
            bool v00 = (j0 >= 0) && (j0 < TT) && (j0 >= tq0 - WW) && (j0 <= tq0 + WW);
            bool v01 = (j1 >= 0) && (j1 < TT) && (j1 >= tq0 - WW) && (j1 <= tq0 + WW);
            bool v10 = (j0 >= 0) && (j0 < TT) && (j0 >= tq1 - WW) && (j0 <= tq1 + WW);
            bool v11 = (j1 >= 0) && (j1 < TT) && (j1 >= tq1 - WW) && (j1 <= tq1 + WW);
            sacc[nt][0] = v00 ? sacc[nt][0] : -CUDART_INF_F;
            sacc[nt][1] = v01 ? sacc[nt][1] : -CUDART_INF_F;
            sacc[nt][2] = v10 ? sacc[nt][2] : -CUDART_INF_F;
            sacc[nt][3] = v11 ? sacc[nt][3] : -CUDART_INF_F;
            rmax0 = fmaxf(rmax0, fmaxf(sacc[nt][0], sacc[nt][1]));
            rmax1 = fmaxf(rmax1, fmaxf(sacc[nt][2], sacc[nt][3]));
        }
        rmax0 = fmaxf(rmax0, __shfl_xor_sync(0xFFFFFFFF, rmax0, 1));
        rmax0 = fmaxf(rmax0, __shfl_xor_sync(0xFFFFFFFF, rmax0, 2));
        rmax1 = fmaxf(rmax1, __shfl_xor_sync(0xFFFFFFFF, rmax1, 1));
        rmax1 = fmaxf(rmax1, __shfl_xor_sync(0xFFFFFFFF, rmax1, 2));

        // online softmax update (NaN-safe for fully-masked rows)
        float mn0 = fmaxf(mr0, rmax0);
        float mn1 = fmaxf(mr1, rmax1);
        bool live0 = (mn0 != -CUDART_INF_F);
        bool live1 = (mn1 != -CUDART_INF_F);
        float alpha0 = live0 ? __expf(mr0 - mn0) : 1.0f;
        float alpha1 = live1 ? __expf(mr1 - mn1) : 1.0f;
        if (live0) mr0 = mn0;
        if (live1) mr1 = mn1;
        l0 *= alpha0;
        l1 *= alpha1;
#pragma unroll
        for (int nt = 0; nt < 8; nt++) {
            oa[nt][0] *= alpha0; oa[nt][1] *= alpha0;
            oa[nt][2] *= alpha1; oa[nt][3] *= alpha1;
        }

        // PV, time-multiplexed: S n-tile kk == PV key-group kk.
        // exp -> tf32 -> quad-shuffle C-frag into A-frag layout -> mma.
#pragma unroll
        for (int kk = 0; kk < 8; kk++) {
            float p0 = live0 ? __expf(sacc[kk][0] - mr0) : 0.0f;
            float p1 = live0 ? __expf(sacc[kk][1] - mr0) : 0.0f;
            float p2 = live1 ? __expf(sacc[kk][2] - mr1) : 0.0f;
            float p3 = live1 ? __expf(sacc[kk][3] - mr1) : 0.0f;
            l0 += p0 + p1;
            l1 += p2 + p3;

            uint32_t c0 = f2tf32(p0), c1 = f2tf32(p1);
            uint32_t c2 = f2tf32(p2), c3 = f2tf32(p3);
            uint32_t v00 = __shfl_sync(0xFFFFFFFF, c0, psrc0);
            uint32_t v01 = __shfl_sync(0xFFFFFFFF, c1, psrc0);
            uint32_t v20 = __shfl_sync(0xFFFFFFFF, c2, psrc0);
            uint32_t v21 = __shfl_sync(0xFFFFFFFF, c3, psrc0);
            uint32_t w00 = __shfl_sync(0xFFFFFFFF, c0, psrc1);
            uint32_t w01 = __shfl_sync(0xFFFFFFFF, c1, psrc1);
            uint32_t w20 = __shfl_sync(0xFFFFFFFF, c2, psrc1);
            uint32_t w21 = __shfl_sync(0xFFFFFFFF, c3, psrc1);

            uint32_t pa[4];
            pa[0] = podd ? v01 : v00;   // P(qr,   qc)
            pa[1] = podd ? v21 : v20;   // P(qr+8, qc)
            pa[2] = podd ? w01 : w00;   // P(qr,   qc+4)
            pa[3] = podd ? w21 : w20;   // P(qr+8, qc+4)
#pragma unroll
            for (int nt = 0; nt < 8; nt++) {
                uint32_t bb[2];
                bb[0] = __float_as_uint(Vs[kk * 8 + qc    ][nt * 8 + qr]);
                bb[1] = __float_as_uint(Vs[kk * 8 + qc + 4][nt * 8 + qr]);
                mma_tf32(oa[nt], pa, bb);
            }
        }
        __syncthreads();   // before next chunk overwrites Ks/Vs
    }

    // l is a per-thread partial over this lane's key-columns; full row
    // denominator = sum over the quad (qc = 0..3).
    l0 += __shfl_xor_sync(0xFFFFFFFF, l0, 1);
    l0 += __shfl_xor_sync(0xFFFFFFFF, l0, 2);
    l1 += __shfl_xor_sync(0xFFFFFFFF, l1, 1);
    l1 += __shfl_xor_sync(0xFFFFFFFF, l1, 2);

    // normalize and write out [b, t, h*64+dim]
    const float inv0 = 1.0f / l0;   // own key always valid -> l > 0
    const float inv1 = 1.0f / l1;
    float* o0 = out + (((long long)b * TT + tq0) * HH + h) * SS;
    float* o1 = out + (((long long)b * TT + tq1) * HH + h) * SS;
#pragma unroll
    for (int nt = 0; nt < 8; nt++) {
        int dim = nt * 8 + qc * 2;
        float2 r0; r0.x = oa[nt][0] * inv0; r0.y = oa[nt][1] * inv0;
        float2 r1; r1.x = oa[nt][2] * inv1; r1.y = oa[nt][3] * inv1;
        *(float2*)&o0[dim] = r0;
        *(float2*)&o1[dim] = r1;
    }
}

// ---------------------------------------------------------------------------
// Launcher (graph-capturable: kernel launches only, no allocs, no syncs)
// ---------------------------------------------------------------------------
extern "C" void kernel_launch(void* const* d_in, const int* in_sizes, int n_in,
                              void* d_out, int out_size)
{
    const float* x  = (const float*)d_in[0];
    const float* Wq = (const float*)d_in[1];
    const float* Wk = (const float*)d_in[2];
    const float* Wv = (const float*)d_in[3];
    float* out = (float*)d_out;

    dim3 g1(MM / 128, EE / 64, 3);   // (64, 12, 3)
    qkv_gemm_tc<<<g1, 256>>>(x, Wq, Wk, Wv);

    dim3 g2(TT / QB, HH, BB);        // (64, 12, 2)
    banded_attn_tc<<<g2, ATH>>>(out);
}